// round 13
// baseline (speedup 1.0000x reference)
#include <cuda_runtime.h>
#include <cuda_fp16.h>
#include <stdint.h>

// ---------------------------------------------------------------------------
// Problem constants
// ---------------------------------------------------------------------------
#define DIN        64
#define HID        256
#define ROWS_TOTAL (256 * 2048)            // 524288
#define WARP_M     16
#define NTHREADS   384
#define NWARPS_CTA (NTHREADS / 32)         // 12
#define GRID_SMS   148
#define NWARPS_TOT (GRID_SMS * NWARPS_CTA) // 1776
#define MIN_VAL    (-1e8f)

// ---------------------------------------------------------------------------
// Device globals: compaction state (self-resetting; no zero_kernel)
// ---------------------------------------------------------------------------
__device__ int g_count = 0;
__device__ int g_done  = 0;
__device__ int g_idx[ROWS_TOTAL];

// ---------------------------------------------------------------------------
// SMEM layout (bytes). Padded strides: odd multiples of 16B -> conflict-free
// ldmatrix row addressing.
// ---------------------------------------------------------------------------
#define XSTRIDE_H  72          // halfs per row (144B = 9*16B)
#define W2STRIDE_H 264         // halfs per row (528B = 33*16B)

#define SM_X      0                                         // 12 * 16*72*2 = 27648
#define SM_W1T    (SM_X + NWARPS_CTA * WARP_M * XSTRIDE_H * 2)
#define SM_W2T    (SM_W1T + HID * XSTRIDE_H * 2)            // + 36864
#define SM_SH     (SM_W2T + HID * W2STRIDE_H * 2)           // + 135168 ; 256 half
#define SM_CH     (SM_SH + 512)                             // 256 half
#define SM_B2     (SM_CH + 512)                             // 256 f32
#define SM_W3     (SM_B2 + 1024)                            // 256 f32
#define SM_TOTAL  (SM_W3 + 1024)

// ---------------------------------------------------------------------------
// Helpers
// ---------------------------------------------------------------------------
__device__ __forceinline__ uint32_t smem_u32(const void* p) {
    uint32_t a;
    asm("{ .reg .u64 t; cvta.to.shared.u64 t, %1; cvt.u32.u64 %0, t; }" : "=r"(a) : "l"(p));
    return a;
}

__device__ __forceinline__ uint32_t h2u(__half2 v) {
    return *reinterpret_cast<uint32_t*>(&v);
}
__device__ __forceinline__ __half2 u2h(uint32_t v) {
    return *reinterpret_cast<__half2*>(&v);
}

__device__ __forceinline__ void ldm4(uint32_t* r, uint32_t addr) {
    asm volatile("ldmatrix.sync.aligned.m8n8.x4.shared.b16 {%0,%1,%2,%3}, [%4];"
                 : "=r"(r[0]), "=r"(r[1]), "=r"(r[2]), "=r"(r[3]) : "r"(addr));
}

__device__ __forceinline__ void prefetch_l2(const void* p) {
    asm volatile("prefetch.global.L2 [%0];" :: "l"(p));
}

// f16-accumulate HMMA: D(16x8 f16) += A(16x16 f16) * B(16x8 f16)
__device__ __forceinline__ void mma_h(uint32_t& c0, uint32_t& c1,
                                      uint32_t a0, uint32_t a1, uint32_t a2, uint32_t a3,
                                      uint32_t b0, uint32_t b1) {
    asm volatile("mma.sync.aligned.m16n8k16.row.col.f16.f16.f16.f16 "
                 "{%0,%1}, {%2,%3,%4,%5}, {%6,%7}, {%0,%1};"
                 : "+r"(c0), "+r"(c1)
                 : "r"(a0), "r"(a1), "r"(a2), "r"(a3), "r"(b0), "r"(b1));
}

// ---------------------------------------------------------------------------
// Kernel 1: init output to MIN_VAL, build compacted index list (warp-agg atomics)
// g_count is zero on entry (static init on first call; main kernel resets it).
// ---------------------------------------------------------------------------
__global__ void prep_kernel(const int* __restrict__ mask, float* __restrict__ out) {
    int row  = blockIdx.x * blockDim.x + threadIdx.x;
    int lane = threadIdx.x & 31;
    out[row] = MIN_VAL;
    bool v = (mask[row] != 0);
    uint32_t bal = __ballot_sync(0xFFFFFFFF, v);
    int base = 0;
    if (lane == 0 && bal) base = atomicAdd(&g_count, __popc(bal));
    base = __shfl_sync(0xFFFFFFFF, base, 0);
    if (v) g_idx[base + __popc(bal & ((1u << lane) - 1u))] = row;
}

// ---------------------------------------------------------------------------
// Main kernel: f16-accumulate HMMA, h1 register-resident, 16 rows/warp.
// Last-finishing CTA resets g_count for the next replay.
// ---------------------------------------------------------------------------
__global__ void __launch_bounds__(NTHREADS, 1) node_mlp_kernel(
    const float* __restrict__ obs,
    const float* __restrict__ W1, const float* __restrict__ b1,
    const float* __restrict__ gamma, const float* __restrict__ beta,
    const float* __restrict__ rmean, const float* __restrict__ rvar,
    const float* __restrict__ W2, const float* __restrict__ b2,
    const float* __restrict__ W3, const float* __restrict__ b3,
    float* __restrict__ out)
{
    extern __shared__ char smem[];
    const uint32_t sb = smem_u32(smem);
    const int tid  = threadIdx.x;
    const int wid  = tid >> 5;
    const int lane = tid & 31;

    // Read count FIRST (all 148 CTAs are co-resident; earliest CTA finish is
    // >> staging time, so this read always precedes any CTA's reset).
    const int cnt = *(volatile int*)&g_count;

    __half* w1t = (__half*)(smem + SM_W1T);
    __half* w2t = (__half*)(smem + SM_W2T);

    // ---- one-time weight staging ----
    for (int idx = tid; idx < DIN * HID; idx += NTHREADS) {
        int k = idx >> 8, n = idx & 255;           // W1[k][n]
        w1t[n * XSTRIDE_H + k] = __float2half(W1[idx]);
    }
    for (int idx = tid; idx < HID * HID; idx += NTHREADS) {
        int k = idx >> 8, n = idx & 255;           // W2[k][n]
        w2t[n * W2STRIDE_H + k] = __float2half(W2[idx]);
    }
    for (int n = tid; n < HID; n += NTHREADS) {
        float s = gamma[n] * rsqrtf(rvar[n] + 1e-5f);
        ((__half*)(smem + SM_SH))[n] = __float2half(s);
        ((__half*)(smem + SM_CH))[n] = __float2half((b1[n] - rmean[n]) * s + beta[n]);
        ((float*)(smem + SM_B2))[n]  = b2[n];
        ((float*)(smem + SM_W3))[n]  = W3[n];
    }
    const float b3v = __ldg(b3);
    __syncthreads();

    const __half* Sh  = (const __half*)(smem + SM_SH);
    const __half* Ch  = (const __half*)(smem + SM_CH);
    const float*  B2v = (const float*)(smem + SM_B2);
    const float*  W3v = (const float*)(smem + SM_W3);

    const int ntiles = (cnt + WARP_M - 1) >> 4;

    const uint32_t xbase = sb + SM_X + wid * (WARP_M * XSTRIDE_H * 2);
    const uint32_t lrow = (uint32_t)(lane & 15);
    const uint32_t lcol = (uint32_t)(lane >> 4) * 16;       // bytes
    const uint32_t a_addr  = xbase + lrow * (XSTRIDE_H * 2) + lcol;
    const uint32_t w1_addr = sb + SM_W1T + lrow * (XSTRIDE_H * 2) + lcol;
    const uint32_t w2_addr = sb + SM_W2T + lrow * (W2STRIDE_H * 2) + lcol;

    const int g  = lane >> 2;           // 0..7 (output row within 8-row group)
    const int t2 = (lane & 3) * 2;      // 0,2,4,6 (output col pair)
    const __half2 zero2 = __float2half2_rn(0.0f);

    const int gwid = blockIdx.x * NWARPS_CTA + wid;

    for (int wt = gwid; wt < ntiles; wt += NWARPS_TOT) {
        const int i0 = wt * WARP_M;

        // ---- gather X 16x64 f32 -> f16 into this warp's smem slab ----
        const int r    = lane >> 1;          // 0..15
        const int hsel = lane & 1;
        {
            const int gi   = min(i0 + r, cnt - 1);
            const int row  = g_idx[gi];
            const float4* src = (const float4*)(obs + (size_t)row * DIN + hsel * 32);
            uint32_t dstoff = (xbase - sb) + (uint32_t)r * (XSTRIDE_H * 2) + (uint32_t)hsel * 64;
            #pragma unroll
            for (int i = 0; i < 8; i++) {
                float4 v = src[i];
                uint2 pk;
                pk.x = h2u(__floats2half2_rn(v.x, v.y));
                pk.y = h2u(__floats2half2_rn(v.z, v.w));
                *(uint2*)(smem + dstoff + i * 8) = pk;
            }
        }
        // ---- L2-prefetch next tile's X rows (hides DRAM latency) ----
        {
            const int gin  = min(i0 + NWARPS_TOT * WARP_M + r, cnt - 1);
            const int rown = g_idx[gin];
            prefetch_l2((const char*)(obs + (size_t)rown * DIN + hsel * 32));
        }
        __syncwarp();

        // ---- A fragments for GEMM1 (4 k-steps of 16) ----
        uint32_t a[4][4];
        #pragma unroll
        for (int kk = 0; kk < 4; kk++) ldm4(a[kk], a_addr + kk * 32);

        // ---- GEMM1 (16x256x64, f16 accum) + BN + ReLU -> h1 in registers ----
        uint32_t h1lo[32], h1hi[32];
        #pragma unroll
        for (int cc = 0; cc < 4; cc++) {
            uint32_t c0[8], c1[8];
            #pragma unroll
            for (int j = 0; j < 8; j++) { c0[j] = 0u; c1[j] = 0u; }
            #pragma unroll
            for (int kk = 0; kk < 4; kk++) {
                #pragma unroll
                for (int p = 0; p < 4; p++) {
                    uint32_t b[4];
                    ldm4(b, w1_addr + (uint32_t)(cc * 64 + 16 * p) * (XSTRIDE_H * 2) + kk * 32);
                    mma_h(c0[2*p],   c1[2*p],   a[kk][0], a[kk][1], a[kk][2], a[kk][3], b[0], b[2]);
                    mma_h(c0[2*p+1], c1[2*p+1], a[kk][0], a[kk][1], a[kk][2], a[kk][3], b[1], b[3]);
                }
            }
            #pragma unroll
            for (int j = 0; j < 8; j++) {
                int n = cc * 64 + 8 * j + t2;
                __half2 s2 = *(const __half2*)(Sh + n);
                __half2 d2 = *(const __half2*)(Ch + n);
                h1lo[cc*8 + j] = h2u(__hmax2(__hfma2(u2h(c0[j]), s2, d2), zero2));
                h1hi[cc*8 + j] = h2u(__hmax2(__hfma2(u2h(c1[j]), s2, d2), zero2));
            }
        }

        // ---- GEMM2 (16x256x256, f16 accum, A from registers) + bias+ReLU+dot ----
        float y0 = 0.0f, y1 = 0.0f;
        for (int cc = 0; cc < 4; cc++) {            // not unrolled (code size)
            uint32_t c0[8], c1[8];
            #pragma unroll
            for (int j = 0; j < 8; j++) { c0[j] = 0u; c1[j] = 0u; }
            uint32_t wbase = w2_addr + (uint32_t)(cc * 64) * (W2STRIDE_H * 2);
            #pragma unroll
            for (int kk = 0; kk < 16; kk++) {
                uint32_t a0 = h1lo[2*kk],   a1 = h1hi[2*kk];
                uint32_t a2 = h1lo[2*kk+1], a3 = h1hi[2*kk+1];
                #pragma unroll
                for (int p = 0; p < 4; p++) {
                    uint32_t b[4];
                    ldm4(b, wbase + (uint32_t)(16 * p) * (W2STRIDE_H * 2) + kk * 32);
                    mma_h(c0[2*p],   c1[2*p],   a0, a1, a2, a3, b[0], b[2]);
                    mma_h(c0[2*p+1], c1[2*p+1], a0, a1, a2, a3, b[1], b[3]);
                }
            }
            #pragma unroll
            for (int j = 0; j < 8; j++) {
                int n = cc * 64 + 8 * j + t2;
                float bb0 = B2v[n], bb1 = B2v[n+1], w30 = W3v[n], w31 = W3v[n+1];
                float2 f0 = __half22float2(u2h(c0[j]));
                float2 f1 = __half22float2(u2h(c1[j]));
                y0 = fmaf(fmaxf(f0.x + bb0, 0.0f), w30, y0);
                y0 = fmaf(fmaxf(f0.y + bb1, 0.0f), w31, y0);
                y1 = fmaf(fmaxf(f1.x + bb0, 0.0f), w30, y1);
                y1 = fmaf(fmaxf(f1.y + bb1, 0.0f), w31, y1);
            }
        }

        // ---- reduce over 4 lanes per row group, scatter ----
        y0 += __shfl_xor_sync(0xFFFFFFFF, y0, 1);
        y0 += __shfl_xor_sync(0xFFFFFFFF, y0, 2);
        y1 += __shfl_xor_sync(0xFFFFFFFF, y1, 1);
        y1 += __shfl_xor_sync(0xFFFFFFFF, y1, 2);
        if ((lane & 3) == 0) {
            int i1 = i0 + g;
            int i2 = i0 + 8 + g;
            if (i1 < cnt) out[g_idx[i1]] = y0 + b3v;
            if (i2 < cnt) out[g_idx[i2]] = y1 + b3v;
        }
        __syncwarp();
    }

    // ---- last-finishing CTA resets the compaction counter for next replay ----
    __syncthreads();
    if (tid == 0) {
        int ticket = atomicAdd(&g_done, 1);
        if (ticket == GRID_SMS - 1) {
            g_count = 0;
            g_done  = 0;
            __threadfence();
        }
    }
}

// ---------------------------------------------------------------------------
// Launch
// ---------------------------------------------------------------------------
extern "C" void kernel_launch(void* const* d_in, const int* in_sizes, int n_in,
                              void* d_out, int out_size)
{
    (void)in_sizes; (void)n_in; (void)out_size;
    cudaFuncSetAttribute(node_mlp_kernel,
                         cudaFuncAttributeMaxDynamicSharedMemorySize, SM_TOTAL);

    prep_kernel<<<ROWS_TOTAL / 256, 256>>>((const int*)d_in[1], (float*)d_out);
    node_mlp_kernel<<<GRID_SMS, NTHREADS, SM_TOTAL>>>(
        (const float*)d_in[0],  // obs
        (const float*)d_in[2],  // W1
        (const float*)d_in[3],  // b1
        (const float*)d_in[4],  // gamma
        (const float*)d_in[5],  // beta
        (const float*)d_in[6],  // run_mean
        (const float*)d_in[7],  // run_var
        (const float*)d_in[8],  // W2
        (const float*)d_in[9],  // b2
        (const float*)d_in[10], // W3
        (const float*)d_in[11], // b3
        (float*)d_out);
}

// round 15
// speedup vs baseline: 1.1293x; 1.1293x over previous
#include <cuda_runtime.h>
#include <cuda_fp16.h>
#include <stdint.h>

// ---------------------------------------------------------------------------
// Problem constants
// ---------------------------------------------------------------------------
#define DIN        64
#define HID        256
#define ROWS_TOTAL (256 * 2048)            // 524288
#define WARP_M     16
#define NTHREADS   512
#define NWARPS_CTA (NTHREADS / 32)         // 16
#define GRID_SMS   148
#define NWARPS_TOT (GRID_SMS * NWARPS_CTA) // 2368
#define MIN_VAL    (-1e8f)

// ---------------------------------------------------------------------------
// Device globals: compaction state (self-resetting; no zero_kernel)
// ---------------------------------------------------------------------------
__device__ int g_count = 0;
__device__ int g_done  = 0;
__device__ int g_idx[ROWS_TOTAL];

// ---------------------------------------------------------------------------
// SMEM layout (bytes). Padded strides: odd multiples of 16B -> conflict-free
// ldmatrix row addressing.
// ---------------------------------------------------------------------------
#define XSTRIDE_H  72          // halfs per row (144B = 9*16B)
#define W2STRIDE_H 264         // halfs per row (528B = 33*16B)

#define SM_X      0                                         // 16 * 16*72*2 = 36864
#define SM_W1T    (SM_X + NWARPS_CTA * WARP_M * XSTRIDE_H * 2)
#define SM_W2T    (SM_W1T + HID * XSTRIDE_H * 2)            // + 36864
#define SM_SH     (SM_W2T + HID * W2STRIDE_H * 2)           // + 135168 ; 256 half
#define SM_CH     (SM_SH + 512)                             // 256 half
#define SM_B2     (SM_CH + 512)                             // 256 f32
#define SM_W3     (SM_B2 + 1024)                            // 256 f32
#define SM_TOTAL  (SM_W3 + 1024)                            // ~212 KB

// ---------------------------------------------------------------------------
// Helpers
// ---------------------------------------------------------------------------
__device__ __forceinline__ uint32_t smem_u32(const void* p) {
    uint32_t a;
    asm("{ .reg .u64 t; cvta.to.shared.u64 t, %1; cvt.u32.u64 %0, t; }" : "=r"(a) : "l"(p));
    return a;
}

__device__ __forceinline__ uint32_t h2u(__half2 v) {
    return *reinterpret_cast<uint32_t*>(&v);
}
__device__ __forceinline__ __half2 u2h(uint32_t v) {
    return *reinterpret_cast<__half2*>(&v);
}

__device__ __forceinline__ void ldm4(uint32_t* r, uint32_t addr) {
    asm volatile("ldmatrix.sync.aligned.m8n8.x4.shared.b16 {%0,%1,%2,%3}, [%4];"
                 : "=r"(r[0]), "=r"(r[1]), "=r"(r[2]), "=r"(r[3]) : "r"(addr));
}

__device__ __forceinline__ void prefetch_l2(const void* p) {
    asm volatile("prefetch.global.L2 [%0];" :: "l"(p));
}

// f16-accumulate HMMA: D(16x8 f16) += A(16x16 f16) * B(16x8 f16)
__device__ __forceinline__ void mma_h(uint32_t& c0, uint32_t& c1,
                                      uint32_t a0, uint32_t a1, uint32_t a2, uint32_t a3,
                                      uint32_t b0, uint32_t b1) {
    asm volatile("mma.sync.aligned.m16n8k16.row.col.f16.f16.f16.f16 "
                 "{%0,%1}, {%2,%3,%4,%5}, {%6,%7}, {%0,%1};"
                 : "+r"(c0), "+r"(c1)
                 : "r"(a0), "r"(a1), "r"(a2), "r"(a3), "r"(b0), "r"(b1));
}

// ---------------------------------------------------------------------------
// Kernel 1: init output to MIN_VAL, build compacted index list (warp-agg atomics)
// ---------------------------------------------------------------------------
__global__ void prep_kernel(const int* __restrict__ mask, float* __restrict__ out) {
    int row  = blockIdx.x * blockDim.x + threadIdx.x;
    int lane = threadIdx.x & 31;
    out[row] = MIN_VAL;
    bool v = (mask[row] != 0);
    uint32_t bal = __ballot_sync(0xFFFFFFFF, v);
    int base = 0;
    if (lane == 0 && bal) base = atomicAdd(&g_count, __popc(bal));
    base = __shfl_sync(0xFFFFFFFF, base, 0);
    if (v) g_idx[base + __popc(bal & ((1u << lane) - 1u))] = row;
}

// ---------------------------------------------------------------------------
// Main kernel: f16-accumulate HMMA, h1 register-resident, 16 rows/warp,
// 16 warps/CTA, software-pipelined B fragments in GEMM2.
// ---------------------------------------------------------------------------
__global__ void __launch_bounds__(NTHREADS, 1) node_mlp_kernel(
    const float* __restrict__ obs,
    const float* __restrict__ W1, const float* __restrict__ b1,
    const float* __restrict__ gamma, const float* __restrict__ beta,
    const float* __restrict__ rmean, const float* __restrict__ rvar,
    const float* __restrict__ W2, const float* __restrict__ b2,
    const float* __restrict__ W3, const float* __restrict__ b3,
    float* __restrict__ out)
{
    extern __shared__ char smem[];
    const uint32_t sb = smem_u32(smem);
    const int tid  = threadIdx.x;
    const int wid  = tid >> 5;
    const int lane = tid & 31;

    // Read count FIRST (all 148 CTAs co-resident; any CTA's reset happens far
    // after every CTA has read it).
    const int cnt = *(volatile int*)&g_count;

    __half* w1t = (__half*)(smem + SM_W1T);
    __half* w2t = (__half*)(smem + SM_W2T);

    // ---- one-time weight staging ----
    for (int idx = tid; idx < DIN * HID; idx += NTHREADS) {
        int k = idx >> 8, n = idx & 255;           // W1[k][n]
        w1t[n * XSTRIDE_H + k] = __float2half(W1[idx]);
    }
    for (int idx = tid; idx < HID * HID; idx += NTHREADS) {
        int k = idx >> 8, n = idx & 255;           // W2[k][n]
        w2t[n * W2STRIDE_H + k] = __float2half(W2[idx]);
    }
    for (int n = tid; n < HID; n += NTHREADS) {
        float s = gamma[n] * rsqrtf(rvar[n] + 1e-5f);
        ((__half*)(smem + SM_SH))[n] = __float2half(s);
        ((__half*)(smem + SM_CH))[n] = __float2half((b1[n] - rmean[n]) * s + beta[n]);
        ((float*)(smem + SM_B2))[n]  = b2[n];
        ((float*)(smem + SM_W3))[n]  = W3[n];
    }
    const float b3v = __ldg(b3);
    __syncthreads();

    const __half* Sh  = (const __half*)(smem + SM_SH);
    const __half* Ch  = (const __half*)(smem + SM_CH);
    const float*  B2v = (const float*)(smem + SM_B2);
    const float*  W3v = (const float*)(smem + SM_W3);

    const int ntiles = (cnt + WARP_M - 1) >> 4;

    const uint32_t xbase = sb + SM_X + wid * (WARP_M * XSTRIDE_H * 2);
    const uint32_t lrow = (uint32_t)(lane & 15);
    const uint32_t lcol = (uint32_t)(lane >> 4) * 16;       // bytes
    const uint32_t a_addr  = xbase + lrow * (XSTRIDE_H * 2) + lcol;
    const uint32_t w1_addr = sb + SM_W1T + lrow * (XSTRIDE_H * 2) + lcol;
    const uint32_t w2_addr = sb + SM_W2T + lrow * (W2STRIDE_H * 2) + lcol;

    const int g  = lane >> 2;           // 0..7 (output row within 8-row group)
    const int t2 = (lane & 3) * 2;      // 0,2,4,6 (output col pair)
    const __half2 zero2 = __float2half2_rn(0.0f);

    const int gwid = blockIdx.x * NWARPS_CTA + wid;

    for (int wt = gwid; wt < ntiles; wt += NWARPS_TOT) {
        const int i0 = wt * WARP_M;

        // ---- gather X 16x64 f32 -> f16 into this warp's smem slab ----
        const int r    = lane >> 1;          // 0..15
        const int hsel = lane & 1;
        {
            const int gi   = min(i0 + r, cnt - 1);
            const int row  = g_idx[gi];
            const float4* src = (const float4*)(obs + (size_t)row * DIN + hsel * 32);
            uint32_t dstoff = (xbase - sb) + (uint32_t)r * (XSTRIDE_H * 2) + (uint32_t)hsel * 64;
            #pragma unroll
            for (int i = 0; i < 8; i++) {
                float4 v = src[i];
                uint2 pk;
                pk.x = h2u(__floats2half2_rn(v.x, v.y));
                pk.y = h2u(__floats2half2_rn(v.z, v.w));
                *(uint2*)(smem + dstoff + i * 8) = pk;
            }
        }
        // ---- L2-prefetch next tile's X rows ----
        {
            const int gin  = min(i0 + NWARPS_TOT * WARP_M + r, cnt - 1);
            const int rown = g_idx[gin];
            prefetch_l2((const char*)(obs + (size_t)rown * DIN + hsel * 32));
        }
        __syncwarp();

        // ---- A fragments for GEMM1 (4 k-steps of 16) ----
        uint32_t a[4][4];
        #pragma unroll
        for (int kk = 0; kk < 4; kk++) ldm4(a[kk], a_addr + kk * 32);

        // ---- GEMM1 (16x256x64, f16 accum) + BN + ReLU -> h1 in registers ----
        uint32_t h1lo[32], h1hi[32];
        #pragma unroll
        for (int cc = 0; cc < 4; cc++) {
            uint32_t c0[8], c1[8];
            #pragma unroll
            for (int j = 0; j < 8; j++) { c0[j] = 0u; c1[j] = 0u; }
            #pragma unroll
            for (int kk = 0; kk < 4; kk++) {
                #pragma unroll
                for (int p = 0; p < 4; p++) {
                    uint32_t b[4];
                    ldm4(b, w1_addr + (uint32_t)(cc * 64 + 16 * p) * (XSTRIDE_H * 2) + kk * 32);
                    mma_h(c0[2*p],   c1[2*p],   a[kk][0], a[kk][1], a[kk][2], a[kk][3], b[0], b[2]);
                    mma_h(c0[2*p+1], c1[2*p+1], a[kk][0], a[kk][1], a[kk][2], a[kk][3], b[1], b[3]);
                }
            }
            #pragma unroll
            for (int j = 0; j < 8; j++) {
                int n = cc * 64 + 8 * j + t2;
                __half2 s2 = *(const __half2*)(Sh + n);
                __half2 d2 = *(const __half2*)(Ch + n);
                h1lo[cc*8 + j] = h2u(__hmax2(__hfma2(u2h(c0[j]), s2, d2), zero2));
                h1hi[cc*8 + j] = h2u(__hmax2(__hfma2(u2h(c1[j]), s2, d2), zero2));
            }
        }

        // ---- GEMM2 (16x256x256, f16 accum, A from registers, B pipelined) ----
        float y0 = 0.0f, y1 = 0.0f;
        for (int cc = 0; cc < 4; cc++) {            // not unrolled (code size)
            uint32_t c0[8], c1[8];
            #pragma unroll
            for (int j = 0; j < 8; j++) { c0[j] = 0u; c1[j] = 0u; }
            const uint32_t wbase = w2_addr + (uint32_t)(cc * 64) * (W2STRIDE_H * 2);

            // software pipeline: load b for i+1 before MMAs of i
            uint32_t bb[2][4];
            ldm4(bb[0], wbase);                     // i=0 : kk=0, p=0
            #pragma unroll
            for (int i = 0; i < 64; i++) {
                const int kk = i >> 2, p = i & 3;
                if (i + 1 < 64) {
                    const int kk2 = (i + 1) >> 2, p2 = (i + 1) & 3;
                    ldm4(bb[(i + 1) & 1],
                         wbase + (uint32_t)(16 * p2) * (W2STRIDE_H * 2) + kk2 * 32);
                }
                const uint32_t a0 = h1lo[2*kk],   a1 = h1hi[2*kk];
                const uint32_t a2 = h1lo[2*kk+1], a3 = h1hi[2*kk+1];
                mma_h(c0[2*p],   c1[2*p],   a0, a1, a2, a3, bb[i & 1][0], bb[i & 1][2]);
                mma_h(c0[2*p+1], c1[2*p+1], a0, a1, a2, a3, bb[i & 1][1], bb[i & 1][3]);
            }

            #pragma unroll
            for (int j = 0; j < 8; j++) {
                int n = cc * 64 + 8 * j + t2;
                float2 bb2 = *(const float2*)(B2v + n);
                float2 w32 = *(const float2*)(W3v + n);
                float2 f0 = __half22float2(u2h(c0[j]));
                float2 f1 = __half22float2(u2h(c1[j]));
                y0 = fmaf(fmaxf(f0.x + bb2.x, 0.0f), w32.x, y0);
                y0 = fmaf(fmaxf(f0.y + bb2.y, 0.0f), w32.y, y0);
                y1 = fmaf(fmaxf(f1.x + bb2.x, 0.0f), w32.x, y1);
                y1 = fmaf(fmaxf(f1.y + bb2.y, 0.0f), w32.y, y1);
            }
        }

        // ---- reduce over 4 lanes per row group, scatter ----
        y0 += __shfl_xor_sync(0xFFFFFFFF, y0, 1);
        y0 += __shfl_xor_sync(0xFFFFFFFF, y0, 2);
        y1 += __shfl_xor_sync(0xFFFFFFFF, y1, 1);
        y1 += __shfl_xor_sync(0xFFFFFFFF, y1, 2);
        if ((lane & 3) == 0) {
            int i1 = i0 + g;
            int i2 = i0 + 8 + g;
            if (i1 < cnt) out[g_idx[i1]] = y0 + b3v;
            if (i2 < cnt) out[g_idx[i2]] = y1 + b3v;
        }
        __syncwarp();
    }

    // ---- last-finishing CTA resets the compaction counter for next replay ----
    __syncthreads();
    if (tid == 0) {
        int ticket = atomicAdd(&g_done, 1);
        if (ticket == GRID_SMS - 1) {
            g_count = 0;
            g_done  = 0;
            __threadfence();
        }
    }
}

// ---------------------------------------------------------------------------
// Launch
// ---------------------------------------------------------------------------
extern "C" void kernel_launch(void* const* d_in, const int* in_sizes, int n_in,
                              void* d_out, int out_size)
{
    (void)in_sizes; (void)n_in; (void)out_size;
    cudaFuncSetAttribute(node_mlp_kernel,
                         cudaFuncAttributeMaxDynamicSharedMemorySize, SM_TOTAL);

    prep_kernel<<<ROWS_TOTAL / 256, 256>>>((const int*)d_in[1], (float*)d_out);
    node_mlp_kernel<<<GRID_SMS, NTHREADS, SM_TOTAL>>>(
        (const float*)d_in[0],  // obs
        (const float*)d_in[2],  // W1
        (const float*)d_in[3],  // b1
        (const float*)d_in[4],  // gamma
        (const float*)d_in[5],  // beta
        (const float*)d_in[6],  // run_mean
        (const float*)d_in[7],  // run_var
        (const float*)d_in[8],  // W2
        (const float*)d_in[9],  // b2
        (const float*)d_in[10], // W3
        (const float*)d_in[11], // b3
        (float*)d_out);
}